// round 1
// baseline (speedup 1.0000x reference)
#include <cuda_runtime.h>
#include <cuda_bf16.h>
#include <cstdint>

// Problem constants
#define TT   4
#define HH   128
#define WW   128
#define CC   256
#define HDN  8
#define KNBR 9
#define FF   32          // CC / HDN
#define MDIM (TT*HH*WW)  // 65536

// Scratch (device globals; no runtime allocation allowed)
__device__ float g_v[(size_t)MDIM * CC];    // v = x @ v_w.T
__device__ float g_agg[(size_t)MDIM * CC];  // attention-aggregated features

// ---------------------------------------------------------------------------
// SGEMM (NT): C[m,n] = sum_k A[m,k] * B[n,k] (+ bias[n])
// A: [M, Kd] row-major, B: [N, Kd] row-major (i.e. computing A @ B^T)
// Block tile 128x128, K-tile 16, 256 threads, 8x8 per thread.
// Requires M%128==0, N%128==0, Kd%16==0 (true here: 65536, 256, 256).
// ---------------------------------------------------------------------------
#define BM 128
#define BN 128
#define BK 16
#define TM 8
#define TN 8

__global__ __launch_bounds__(256, 2)
void sgemm_nt_kernel(const float* __restrict__ A,
                     const float* __restrict__ B,
                     const float* __restrict__ bias,
                     float* __restrict__ C,
                     int M, int N, int Kd)
{
    __shared__ float As[BK][BM];
    __shared__ float Bs[BK][BN];

    const int tid = threadIdx.x;
    const int bm  = blockIdx.y * BM;
    const int bn  = blockIdx.x * BN;

    const int tr = tid >> 4;   // 0..15  (thread row in 16x16 thread grid)
    const int tc = tid & 15;   // 0..15

    float acc[TM][TN];
    #pragma unroll
    for (int i = 0; i < TM; i++)
        #pragma unroll
        for (int j = 0; j < TN; j++)
            acc[i][j] = 0.0f;

    for (int k0 = 0; k0 < Kd; k0 += BK) {
        // Load A tile (BM x BK) and B tile (BN x BK), both K-contiguous.
        // 128*16 floats = 512 float4 per tile; 256 threads -> 2 float4 each.
        #pragma unroll
        for (int i = 0; i < 2; i++) {
            int idx  = tid * 2 + i;         // 0..511
            int row  = idx >> 2;            // 0..127
            int col4 = (idx & 3) << 2;      // 0,4,8,12

            float4 av = *(const float4*)(A + (size_t)(bm + row) * Kd + k0 + col4);
            As[col4 + 0][row] = av.x;
            As[col4 + 1][row] = av.y;
            As[col4 + 2][row] = av.z;
            As[col4 + 3][row] = av.w;

            float4 bv = *(const float4*)(B + (size_t)(bn + row) * Kd + k0 + col4);
            Bs[col4 + 0][row] = bv.x;
            Bs[col4 + 1][row] = bv.y;
            Bs[col4 + 2][row] = bv.z;
            Bs[col4 + 3][row] = bv.w;
        }
        __syncthreads();

        #pragma unroll
        for (int k = 0; k < BK; k++) {
            float af[TM], bf[TN];
            #pragma unroll
            for (int i = 0; i < TM; i++) af[i] = As[k][tr * TM + i];
            #pragma unroll
            for (int j = 0; j < TN; j++) bf[j] = Bs[k][tc * TN + j];
            #pragma unroll
            for (int i = 0; i < TM; i++)
                #pragma unroll
                for (int j = 0; j < TN; j++)
                    acc[i][j] += af[i] * bf[j];
        }
        __syncthreads();
    }

    // Epilogue
    #pragma unroll
    for (int i = 0; i < TM; i++) {
        int m = bm + tr * TM + i;
        #pragma unroll
        for (int j = 0; j < TN; j += 4) {
            int n = bn + tc * TN + j;
            float4 o;
            o.x = acc[i][j + 0];
            o.y = acc[i][j + 1];
            o.z = acc[i][j + 2];
            o.w = acc[i][j + 3];
            if (bias) {
                o.x += bias[n + 0];
                o.y += bias[n + 1];
                o.z += bias[n + 2];
                o.w += bias[n + 3];
            }
            *(float4*)(C + (size_t)m * N + n) = o;
        }
    }
}

// ---------------------------------------------------------------------------
// Flow-guided non-local gather + attention-weighted aggregation.
// One warp per (hd, t, h, w); lane = feature index f (F == 32 exactly).
// agg[t,h,w, hd*F+f] = sum_k attn[hd,t,h,w,k] * v[tt,hh,ww, hd*F+f]
// ---------------------------------------------------------------------------
__global__ __launch_bounds__(256)
void gather_agg_kernel(const float* __restrict__ v,
                       const float* __restrict__ attn,
                       const int*   __restrict__ flows,
                       float* __restrict__ agg)
{
    const int gwarp = (blockIdx.x * blockDim.x + threadIdx.x) >> 5;
    const int lane  = threadIdx.x & 31;
    // gwarp in [0, HDN*TT*HH*WW)
    int tmp = gwarp;
    const int w  = tmp % WW; tmp /= WW;
    const int h  = tmp % HH; tmp /= HH;
    const int t  = tmp % TT;
    const int hd = tmp / TT;

    const size_t abase = (size_t)gwarp * KNBR;       // attn: [...,K]
    const size_t fbase = abase * 3;                  // flows: [...,K,3]

    float acc = 0.0f;
    #pragma unroll
    for (int k = 0; k < KNBR; k++) {
        const float wk = attn[abase + k];
        const int dt = flows[fbase + k * 3 + 0];
        const int dh = flows[fbase + k * 3 + 1];
        const int dw = flows[fbase + k * 3 + 2];
        const int tt = min(max(t + dt, 0), TT - 1);
        const int hh = min(max(h + dh, 0), HH - 1);
        const int ww = min(max(w + dw, 0), WW - 1);
        const size_t vidx = ((size_t)((tt * HH + hh) * WW + ww)) * CC + hd * FF + lane;
        acc += wk * v[vidx];
    }

    const size_t oidx = ((size_t)((t * HH + h) * WW + w)) * CC + hd * FF + lane;
    agg[oidx] = acc;
}

// ---------------------------------------------------------------------------
// Launch
// ---------------------------------------------------------------------------
extern "C" void kernel_launch(void* const* d_in, const int* in_sizes, int n_in,
                              void* d_out, int out_size)
{
    const float* x      = (const float*)d_in[0];  // [T,H,W,C]
    const float* attn   = (const float*)d_in[1];  // [1,HD,T,H,W,K]
    const int*   flows  = (const int*)  d_in[2];  // [1,HD,T,H,W,K,3]
    const float* v_w    = (const float*)d_in[3];  // [C,C]
    const float* proj_w = (const float*)d_in[4];  // [C,C]
    const float* proj_b = (const float*)d_in[5];  // [C]
    float* out = (float*)d_out;                   // [T,H,W,C]

    float* v_buf;
    float* agg_buf;
    cudaGetSymbolAddress((void**)&v_buf,   g_v);
    cudaGetSymbolAddress((void**)&agg_buf, g_agg);

    // 1) v = x @ v_w.T
    {
        dim3 grid(CC / BN, MDIM / BM);   // (2, 512)
        sgemm_nt_kernel<<<grid, 256>>>(x, v_w, nullptr, v_buf, MDIM, CC, CC);
    }

    // 2) flow-guided gather + weighted aggregation
    {
        const int total_warps = HDN * TT * HH * WW;       // 524288
        const int blocks = total_warps / 8;               // 256 threads = 8 warps
        gather_agg_kernel<<<blocks, 256>>>(v_buf, attn, flows, agg_buf);
    }

    // 3) out = agg @ proj_w.T + proj_b
    {
        dim3 grid(CC / BN, MDIM / BM);
        sgemm_nt_kernel<<<grid, 256>>>(agg_buf, proj_w, proj_b, out, MDIM, CC, CC);
    }
}

// round 4
// speedup vs baseline: 2.7653x; 2.7653x over previous
#include <cuda_runtime.h>
#include <cstdint>

// -------------------- problem constants --------------------
#define TT   4
#define HH   128
#define WW   128
#define CC   256
#define HDN  8
#define KNBR 9
#define FF   32
#define MDIM (TT*HH*WW)   // 65536

// scratch (device globals; no runtime allocation allowed)
__device__ float g_v[(size_t)MDIM * CC];
__device__ float g_agg[(size_t)MDIM * CC];

// -------------------- helpers --------------------
__device__ __forceinline__ uint32_t smem_u32(const void* p) {
    uint32_t a;
    asm("{ .reg .u64 t; cvta.to.shared.u64 t, %1; cvt.u32.u64 %0, t; }" : "=r"(a) : "l"(p));
    return a;
}
// f32 -> tf32 (round-to-nearest-even on 10-bit mantissa); result is a b32 bit pattern
__device__ __forceinline__ uint32_t f2tf32(float x) {
    uint32_t r; asm("cvt.rna.tf32.f32 %0, %1;" : "=r"(r) : "f"(x)); return r;
}
// Swizzle<3,4,3>: XOR 16B-chunk index (bits[6:4]) with row%8 (bits[9:7]); row stride 128B
__device__ __forceinline__ uint32_t swz(uint32_t off) {
    return off ^ ((off >> 3) & 0x70);
}

__device__ __forceinline__ void ldmatrix_x4(uint32_t& r0, uint32_t& r1, uint32_t& r2, uint32_t& r3,
                                            uint32_t addr) {
    asm volatile("ldmatrix.sync.aligned.m8n8.x4.shared.b16 {%0,%1,%2,%3}, [%4];"
                 : "=r"(r0), "=r"(r1), "=r"(r2), "=r"(r3) : "r"(addr));
}
__device__ __forceinline__ void mma_tf32(float& c0, float& c1, float& c2, float& c3,
                                         uint32_t a0, uint32_t a1, uint32_t a2, uint32_t a3,
                                         uint32_t b0, uint32_t b1) {
    asm volatile("mma.sync.aligned.m16n8k8.row.col.f32.tf32.tf32.f32 "
                 "{%0,%1,%2,%3}, {%4,%5,%6,%7}, {%8,%9}, {%0,%1,%2,%3};"
                 : "+f"(c0), "+f"(c1), "+f"(c2), "+f"(c3)
                 : "r"(a0), "r"(a1), "r"(a2), "r"(a3), "r"(b0), "r"(b1));
}

// -------------------- tf32 mma.sync GEMM --------------------
// C[m,n] = sum_k A[m,k]*B[n,k] (+bias[n]); M=65536, N=256, K=256.
// CTA tile 128x128, BK=32, double-buffered smem, 8 warps in 2(m) x 4(n),
// warp tile 64x32 => 4 m16 x 4 n8 tiles of m16n8k8 tf32 mma.
#define GEMM_BM 128
#define GEMM_BN 128
#define GEMM_BK 32
#define TILE_BYTES (128 * 32 * 4)          // 16 KB (rows x BK floats)
#define BUF_BYTES  (2 * TILE_BYTES)        // A+B one stage
#define DSMEM_BYTES (2 * BUF_BYTES)        // double buffer = 64 KB

__global__ __launch_bounds__(256, 1)
void gemm_tf32_mma_kernel(const float* __restrict__ A,
                          const float* __restrict__ Bw,
                          const float* __restrict__ bias,
                          float* __restrict__ C)
{
    extern __shared__ char sm[];
    const int tid = threadIdx.x;
    const int wid = tid >> 5;
    const int lane = tid & 31;
    const int warp_m = wid >> 2;      // 0..1
    const int warp_n = wid & 3;       // 0..3
    const int bm = blockIdx.y * GEMM_BM;
    const int bn = blockIdx.x * GEMM_BN;

    const uint32_t smbase = smem_u32(sm);
    // buffer b: A at b*BUF_BYTES, B at b*BUF_BYTES + TILE_BYTES

    // staging indices: thread t handles float4 id f = t + i*256, i=0..3
    const int st_c4  = tid & 7;                  // float4 col within 32-float row
    const int st_row0 = tid >> 3;                // rows st_row0 + 32*i
    const uint32_t st_off = swz((uint32_t)st_row0 * 128 + st_c4 * 16);

    float4 pa[4], pb[4];

    // prologue: load k-tile 0
    {
        const float* Ap = A + (size_t)(bm + st_row0) * CC + st_c4 * 4;
        const float* Bp = Bw + (size_t)(bn + st_row0) * CC + st_c4 * 4;
        #pragma unroll
        for (int i = 0; i < 4; i++) {
            pa[i] = *(const float4*)(Ap + (size_t)i * 32 * CC);
            pb[i] = *(const float4*)(Bp + (size_t)i * 32 * CC);
        }
        #pragma unroll
        for (int i = 0; i < 4; i++) {
            uint4 a, b;
            a.x = f2tf32(pa[i].x); a.y = f2tf32(pa[i].y);
            a.z = f2tf32(pa[i].z); a.w = f2tf32(pa[i].w);
            b.x = f2tf32(pb[i].x); b.y = f2tf32(pb[i].y);
            b.z = f2tf32(pb[i].z); b.w = f2tf32(pb[i].w);
            *(uint4*)(sm + (st_off + i * 32 * 128))              = a;
            *(uint4*)(sm + TILE_BYTES + (st_off + i * 32 * 128)) = b;
        }
    }
    __syncthreads();

    float acc[4][4][4];
    #pragma unroll
    for (int mt = 0; mt < 4; mt++)
        #pragma unroll
        for (int nt = 0; nt < 4; nt++)
            #pragma unroll
            for (int r = 0; r < 4; r++)
                acc[mt][nt][r] = 0.0f;

    // ldmatrix per-lane address components
    const int a_row_in = (lane & 7) + ((lane >> 3) & 1) * 8;   // row within m16 tile
    const int a_chunk_hi = (lane >> 4);                        // +0/+1 chunk (k half)
    const int b_nt_off = (lane >> 4) * 8;                      // ntile pair offset rows
    const int b_row_in = (lane & 7);
    const int b_chunk_hi = (lane >> 3) & 1;

    const int NKT = CC / GEMM_BK;   // 8

    for (int kt = 0; kt < NKT; kt++) {
        // prefetch next k-tile
        if (kt + 1 < NKT) {
            const float* Ap = A + (size_t)(bm + st_row0) * CC + (kt + 1) * GEMM_BK + st_c4 * 4;
            const float* Bp = Bw + (size_t)(bn + st_row0) * CC + (kt + 1) * GEMM_BK + st_c4 * 4;
            #pragma unroll
            for (int i = 0; i < 4; i++) {
                pa[i] = *(const float4*)(Ap + (size_t)i * 32 * CC);
                pb[i] = *(const float4*)(Bp + (size_t)i * 32 * CC);
            }
        }

        // compute on buffer kt&1
        const uint32_t abuf = smbase + (kt & 1) * BUF_BYTES;
        const uint32_t bbuf = abuf + TILE_BYTES;

        #pragma unroll
        for (int kk = 0; kk < 4; kk++) {          // 4 k8-steps in BK=32
            uint32_t af[4][4];
            #pragma unroll
            for (int mt = 0; mt < 4; mt++) {
                const int row = warp_m * 64 + mt * 16 + a_row_in;
                const uint32_t off = swz((uint32_t)row * 128 + (kk * 2 + a_chunk_hi) * 16);
                ldmatrix_x4(af[mt][0], af[mt][1], af[mt][2], af[mt][3], abuf + off);
            }
            uint32_t bf[4][2];
            #pragma unroll
            for (int pair = 0; pair < 2; pair++) { // ntiles {0,1} then {2,3}
                const int row = warp_n * 32 + pair * 16 + b_nt_off + b_row_in;
                const uint32_t off = swz((uint32_t)row * 128 + (kk * 2 + b_chunk_hi) * 16);
                uint32_t r0, r1, r2, r3;
                ldmatrix_x4(r0, r1, r2, r3, bbuf + off);
                bf[pair * 2 + 0][0] = r0; bf[pair * 2 + 0][1] = r1;
                bf[pair * 2 + 1][0] = r2; bf[pair * 2 + 1][1] = r3;
            }
            #pragma unroll
            for (int mt = 0; mt < 4; mt++)
                #pragma unroll
                for (int nt = 0; nt < 4; nt++)
                    mma_tf32(acc[mt][nt][0], acc[mt][nt][1], acc[mt][nt][2], acc[mt][nt][3],
                             af[mt][0], af[mt][1], af[mt][2], af[mt][3],
                             bf[nt][0], bf[nt][1]);
        }

        // store prefetched tile into the other buffer
        if (kt + 1 < NKT) {
            char* dst = sm + ((kt + 1) & 1) * BUF_BYTES;
            #pragma unroll
            for (int i = 0; i < 4; i++) {
                uint4 a, b;
                a.x = f2tf32(pa[i].x); a.y = f2tf32(pa[i].y);
                a.z = f2tf32(pa[i].z); a.w = f2tf32(pa[i].w);
                b.x = f2tf32(pb[i].x); b.y = f2tf32(pb[i].y);
                b.z = f2tf32(pb[i].z); b.w = f2tf32(pb[i].w);
                *(uint4*)(dst + (st_off + i * 32 * 128))              = a;
                *(uint4*)(dst + TILE_BYTES + (st_off + i * 32 * 128)) = b;
            }
        }
        __syncthreads();
    }

    // epilogue: c0,c1 at (row, col..col+1), c2,c3 at (row+8, col..col+1)
    const int er = warp_m * 64 + (lane >> 2);
    const int ec = warp_n * 32 + (lane & 3) * 2;
    #pragma unroll
    for (int mt = 0; mt < 4; mt++) {
        #pragma unroll
        for (int nt = 0; nt < 4; nt++) {
            const int row = bm + er + mt * 16;
            const int col = bn + ec + nt * 8;
            float2 lo = make_float2(acc[mt][nt][0], acc[mt][nt][1]);
            float2 hi = make_float2(acc[mt][nt][2], acc[mt][nt][3]);
            if (bias) {
                const float b0 = bias[col], b1 = bias[col + 1];
                lo.x += b0; lo.y += b1; hi.x += b0; hi.y += b1;
            }
            *(float2*)(C + (size_t)row * CC + col)       = lo;
            *(float2*)(C + (size_t)(row + 8) * CC + col) = hi;
        }
    }
}

// -------------------- flow-guided gather + aggregation --------------------
// warp = 4 consecutive w positions of one (hd,t,h); lane: pos = lane>>3, f-quad = lane&7
__global__ __launch_bounds__(256)
void gather_agg_kernel(const float* __restrict__ v,
                       const float* __restrict__ attn,
                       const int*   __restrict__ flows,
                       float* __restrict__ agg)
{
    const int gwarp = (blockIdx.x * blockDim.x + threadIdx.x) >> 5;
    const int lane  = threadIdx.x & 31;
    const int p     = lane >> 3;        // 0..3
    const int fq    = lane & 7;         // float4 index in 32 features

    int tmp = gwarp;
    const int w4 = (tmp % (WW / 4)) * 4; tmp /= (WW / 4);
    const int h  = tmp % HH; tmp /= HH;
    const int t  = tmp % TT;
    const int hd = tmp / TT;

    const int w = w4 + p;
    const int pos = ((hd * TT + t) * HH + h) * WW + w;   // attn/flows linear pos
    const size_t abase = (size_t)pos * KNBR;
    const size_t fbase = (size_t)pos * (KNBR * 3);

    float4 acc = make_float4(0.f, 0.f, 0.f, 0.f);
    #pragma unroll
    for (int k = 0; k < KNBR; k++) {
        const float wk = __ldg(attn + abase + k);
        const int dt = __ldg(flows + fbase + k * 3 + 0);
        const int dh = __ldg(flows + fbase + k * 3 + 1);
        const int dw = __ldg(flows + fbase + k * 3 + 2);
        const int tt = min(max(t + dt, 0), TT - 1);
        const int hh = min(max(h + dh, 0), HH - 1);
        const int ww = min(max(w + dw, 0), WW - 1);
        const float4 vv = *(const float4*)(v +
            ((size_t)((tt * HH + hh) * WW + ww)) * CC + hd * FF + fq * 4);
        acc.x += wk * vv.x; acc.y += wk * vv.y;
        acc.z += wk * vv.z; acc.w += wk * vv.w;
    }
    *(float4*)(agg + ((size_t)((t * HH + h) * WW + w)) * CC + hd * FF + fq * 4) = acc;
}

// -------------------- launch --------------------
extern "C" void kernel_launch(void* const* d_in, const int* in_sizes, int n_in,
                              void* d_out, int out_size)
{
    const float* x      = (const float*)d_in[0];
    const float* attn   = (const float*)d_in[1];
    const int*   flows  = (const int*)  d_in[2];
    const float* v_w    = (const float*)d_in[3];
    const float* proj_w = (const float*)d_in[4];
    const float* proj_b = (const float*)d_in[5];
    float* out = (float*)d_out;

    float* v_buf;
    float* agg_buf;
    cudaGetSymbolAddress((void**)&v_buf,   g_v);
    cudaGetSymbolAddress((void**)&agg_buf, g_agg);

    cudaFuncSetAttribute(gemm_tf32_mma_kernel,
                         cudaFuncAttributeMaxDynamicSharedMemorySize, DSMEM_BYTES);

    dim3 ggrid(CC / GEMM_BN, MDIM / GEMM_BM);   // (2, 512)

    // 1) v = x @ v_w.T
    gemm_tf32_mma_kernel<<<ggrid, 256, DSMEM_BYTES>>>(x, v_w, nullptr, v_buf);

    // 2) gather + weighted aggregation (warp = 4 positions, float4 lanes)
    {
        const int total_warps = HDN * TT * HH * WW / 4;   // 131072
        gather_agg_kernel<<<total_warps / 8, 256>>>(v_buf, attn, flows, agg_buf);
    }

    // 3) out = agg @ proj_w.T + proj_b
    gemm_tf32_mma_kernel<<<ggrid, 256, DSMEM_BYTES>>>(agg_buf, proj_w, proj_b, out);
}

// round 6
// speedup vs baseline: 3.1034x; 1.1223x over previous
#include <cuda_runtime.h>
#include <cstdint>

// -------------------- problem constants --------------------
#define TT   4
#define HH   128
#define WW   128
#define CC   256
#define HDN  8
#define KNBR 9
#define FF   32
#define MDIM (TT*HH*WW)   // 65536

// scratch (device globals; no runtime allocation allowed)
__device__ float g_xt[(size_t)MDIM * CC];    // x pre-rounded to tf32
__device__ float g_wv[(size_t)CC * CC];      // v_w pre-rounded
__device__ float g_wp[(size_t)CC * CC];      // proj_w pre-rounded
__device__ float g_v[(size_t)MDIM * CC];     // v = x @ v_w.T
__device__ float g_agg[(size_t)MDIM * CC];   // aggregated (tf32-rounded)

// -------------------- helpers --------------------
__device__ __forceinline__ uint32_t smem_u32(const void* p) {
    uint32_t a;
    asm("{ .reg .u64 t; cvta.to.shared.u64 t, %1; cvt.u32.u64 %0, t; }" : "=r"(a) : "l"(p));
    return a;
}
// f32 -> tf32 (RNA); result is b32 bit pattern
__device__ __forceinline__ uint32_t f2tf32(float x) {
    uint32_t r; asm("cvt.rna.tf32.f32 %0, %1;" : "=r"(r) : "f"(x)); return r;
}
// Swizzle<3,4,3>
__device__ __forceinline__ uint32_t swz(uint32_t off) {
    return off ^ ((off >> 3) & 0x70);
}
__device__ __forceinline__ void cp_async16(uint32_t dst, const void* src) {
    asm volatile("cp.async.cg.shared.global [%0], [%1], 16;" :: "r"(dst), "l"(src));
}
__device__ __forceinline__ void cp_commit() {
    asm volatile("cp.async.commit_group;" ::: "memory");
}
template <int N>
__device__ __forceinline__ void cp_wait() {
    asm volatile("cp.async.wait_group %0;" :: "n"(N) : "memory");
}

__device__ __forceinline__ void ldmatrix_x4(uint32_t& r0, uint32_t& r1, uint32_t& r2, uint32_t& r3,
                                            uint32_t addr) {
    asm volatile("ldmatrix.sync.aligned.m8n8.x4.shared.b16 {%0,%1,%2,%3}, [%4];"
                 : "=r"(r0), "=r"(r1), "=r"(r2), "=r"(r3) : "r"(addr));
}
__device__ __forceinline__ void mma_tf32(float& c0, float& c1, float& c2, float& c3,
                                         uint32_t a0, uint32_t a1, uint32_t a2, uint32_t a3,
                                         uint32_t b0, uint32_t b1) {
    asm volatile("mma.sync.aligned.m16n8k8.row.col.f32.tf32.tf32.f32 "
                 "{%0,%1,%2,%3}, {%4,%5,%6,%7}, {%8,%9}, {%0,%1,%2,%3};"
                 : "+f"(c0), "+f"(c1), "+f"(c2), "+f"(c3)
                 : "r"(a0), "r"(a1), "r"(a2), "r"(a3), "r"(b0), "r"(b1));
}

// -------------------- tf32 pre-conversion pass --------------------
__global__ __launch_bounds__(256)
void cvt_tf32_kernel(const float* __restrict__ in, float* __restrict__ out, int n4) {
    int i = blockIdx.x * blockDim.x + threadIdx.x;
    if (i < n4) {
        float4 v = ((const float4*)in)[i];
        uint4 o;
        o.x = f2tf32(v.x); o.y = f2tf32(v.y);
        o.z = f2tf32(v.z); o.w = f2tf32(v.w);
        ((uint4*)out)[i] = o;
    }
}

// -------------------- tf32 mma.sync GEMM (cp.async, 3-stage) --------------------
// Inputs A,B already tf32-rounded (bit patterns in float storage).
// C[m,n] = sum_k A[m,k]*B[n,k] (+bias[n]); M=65536, N=256, K=256.
// CTA tile 128x128, BK=32, 3-stage cp.async pipeline, 8 warps 2(m)x4(n),
// warp tile 64x32.
#define GEMM_BM 128
#define GEMM_BN 128
#define GEMM_BK 32
#define TILE_BYTES (128 * 32 * 4)          // 16 KB
#define BUF_BYTES  (2 * TILE_BYTES)        // A+B per stage = 32 KB
#define NSTAGE 3
#define DSMEM_BYTES (NSTAGE * BUF_BYTES)   // 96 KB
#define NKT (CC / GEMM_BK)                 // 8

__global__ __launch_bounds__(256, 2)
void gemm_tf32_mma_kernel(const float* __restrict__ A,
                          const float* __restrict__ Bw,
                          const float* __restrict__ bias,
                          float* __restrict__ C)
{
    extern __shared__ char sm[];
    const int tid = threadIdx.x;
    const int wid = tid >> 5;
    const int lane = tid & 31;
    const int warp_m = wid >> 2;      // 0..1
    const int warp_n = wid & 3;       // 0..3
    const int bm = blockIdx.y * GEMM_BM;
    const int bn = blockIdx.x * GEMM_BN;

    const uint32_t smbase = smem_u32(sm);

    // staging: thread handles float4 col st_c4 of rows st_row0 + 32*i
    const int st_c4  = tid & 7;
    const int st_row0 = tid >> 3;
    uint32_t st_off[4];
    #pragma unroll
    for (int i = 0; i < 4; i++)
        st_off[i] = swz((uint32_t)(st_row0 + 32 * i) * 128 + st_c4 * 16);

    const float* Abase = A + (size_t)(bm + st_row0) * CC + st_c4 * 4;
    const float* Bbase = Bw + (size_t)(bn + st_row0) * CC + st_c4 * 4;

    // prologue: issue stages 0 and 1
    #pragma unroll
    for (int s = 0; s < 2; s++) {
        const uint32_t abuf = smbase + s * BUF_BYTES;
        #pragma unroll
        for (int i = 0; i < 4; i++) {
            cp_async16(abuf + st_off[i],              Abase + (size_t)i * 32 * CC + s * GEMM_BK);
            cp_async16(abuf + TILE_BYTES + st_off[i], Bbase + (size_t)i * 32 * CC + s * GEMM_BK);
        }
        cp_commit();
    }

    float acc[4][4][4];
    #pragma unroll
    for (int mt = 0; mt < 4; mt++)
        #pragma unroll
        for (int nt = 0; nt < 4; nt++)
            #pragma unroll
            for (int r = 0; r < 4; r++)
                acc[mt][nt][r] = 0.0f;

    // ldmatrix per-lane address components
    const int a_row_in = (lane & 7) + ((lane >> 3) & 1) * 8;
    const int a_chunk_hi = (lane >> 4);
    const int b_nt_off = (lane >> 4) * 8;
    const int b_row_in = (lane & 7);
    const int b_chunk_hi = (lane >> 3) & 1;

    #pragma unroll
    for (int kt = 0; kt < NKT; kt++) {
        if (kt + 1 < NKT) cp_wait<1>(); else cp_wait<0>();
        __syncthreads();

        // issue stage kt+2 (its buffer was freed by compute of kt-1)
        if (kt + 2 < NKT) {
            const uint32_t abuf = smbase + ((kt + 2) % NSTAGE) * BUF_BYTES;
            #pragma unroll
            for (int i = 0; i < 4; i++) {
                cp_async16(abuf + st_off[i],              Abase + (size_t)i * 32 * CC + (kt + 2) * GEMM_BK);
                cp_async16(abuf + TILE_BYTES + st_off[i], Bbase + (size_t)i * 32 * CC + (kt + 2) * GEMM_BK);
            }
            cp_commit();
        }

        const uint32_t abuf = smbase + (kt % NSTAGE) * BUF_BYTES;
        const uint32_t bbuf = abuf + TILE_BYTES;

        #pragma unroll
        for (int kk = 0; kk < 4; kk++) {
            uint32_t af[4][4];
            #pragma unroll
            for (int mt = 0; mt < 4; mt++) {
                const int row = warp_m * 64 + mt * 16 + a_row_in;
                const uint32_t off = swz((uint32_t)row * 128 + (kk * 2 + a_chunk_hi) * 16);
                ldmatrix_x4(af[mt][0], af[mt][1], af[mt][2], af[mt][3], abuf + off);
            }
            uint32_t bf[4][2];
            #pragma unroll
            for (int pair = 0; pair < 2; pair++) {
                const int row = warp_n * 32 + pair * 16 + b_nt_off + b_row_in;
                const uint32_t off = swz((uint32_t)row * 128 + (kk * 2 + b_chunk_hi) * 16);
                uint32_t r0, r1, r2, r3;
                ldmatrix_x4(r0, r1, r2, r3, bbuf + off);
                bf[pair * 2 + 0][0] = r0; bf[pair * 2 + 0][1] = r1;
                bf[pair * 2 + 1][0] = r2; bf[pair * 2 + 1][1] = r3;
            }
            #pragma unroll
            for (int mt = 0; mt < 4; mt++)
                #pragma unroll
                for (int nt = 0; nt < 4; nt++)
                    mma_tf32(acc[mt][nt][0], acc[mt][nt][1], acc[mt][nt][2], acc[mt][nt][3],
                             af[mt][0], af[mt][1], af[mt][2], af[mt][3],
                             bf[nt][0], bf[nt][1]);
        }
        __syncthreads();
    }

    // epilogue
    const int er = warp_m * 64 + (lane >> 2);
    const int ec = warp_n * 32 + (lane & 3) * 2;
    #pragma unroll
    for (int mt = 0; mt < 4; mt++) {
        #pragma unroll
        for (int nt = 0; nt < 4; nt++) {
            const int row = bm + er + mt * 16;
            const int col = bn + ec + nt * 8;
            float2 lo = make_float2(acc[mt][nt][0], acc[mt][nt][1]);
            float2 hi = make_float2(acc[mt][nt][2], acc[mt][nt][3]);
            if (bias) {
                const float b0 = bias[col], b1 = bias[col + 1];
                lo.x += b0; lo.y += b1; hi.x += b0; hi.y += b1;
            }
            *(float2*)(C + (size_t)row * CC + col)       = lo;
            *(float2*)(C + (size_t)(row + 8) * CC + col) = hi;
        }
    }
}

// -------------------- flow-guided gather + aggregation --------------------
// warp = 4 consecutive w positions; lane: pos = lane>>3, f-quad = lane&7.
// Output is tf32-rounded (consumed only by GEMM-2).
__global__ __launch_bounds__(256)
void gather_agg_kernel(const float* __restrict__ v,
                       const float* __restrict__ attn,
                       const int*   __restrict__ flows,
                       float* __restrict__ agg)
{
    const int gwarp = (blockIdx.x * blockDim.x + threadIdx.x) >> 5;
    const int lane  = threadIdx.x & 31;
    const int p     = lane >> 3;
    const int fq    = lane & 7;

    int tmp = gwarp;
    const int w4 = (tmp % (WW / 4)) * 4; tmp /= (WW / 4);
    const int h  = tmp % HH; tmp /= HH;
    const int t  = tmp % TT;
    const int hd = tmp / TT;

    const int w = w4 + p;
    const int pos = ((hd * TT + t) * HH + h) * WW + w;
    const size_t abase = (size_t)pos * KNBR;
    const size_t fbase = (size_t)pos * (KNBR * 3);

    float4 acc = make_float4(0.f, 0.f, 0.f, 0.f);
    #pragma unroll
    for (int k = 0; k < KNBR; k++) {
        const float wk = __ldg(attn + abase + k);
        const int dt = __ldg(flows + fbase + k * 3 + 0);
        const int dh = __ldg(flows + fbase + k * 3 + 1);
        const int dw = __ldg(flows + fbase + k * 3 + 2);
        const int tt = min(max(t + dt, 0), TT - 1);
        const int hh = min(max(h + dh, 0), HH - 1);
        const int ww = min(max(w + dw, 0), WW - 1);
        const float4 vv = *(const float4*)(v +
            ((size_t)((tt * HH + hh) * WW + ww)) * CC + hd * FF + fq * 4);
        acc.x += wk * vv.x; acc.y += wk * vv.y;
        acc.z += wk * vv.z; acc.w += wk * vv.w;
    }
    uint4 o;
    o.x = f2tf32(acc.x); o.y = f2tf32(acc.y);
    o.z = f2tf32(acc.z); o.w = f2tf32(acc.w);
    *(uint4*)(agg + ((size_t)((t * HH + h) * WW + w)) * CC + hd * FF + fq * 4) = o;
}

// -------------------- launch --------------------
extern "C" void kernel_launch(void* const* d_in, const int* in_sizes, int n_in,
                              void* d_out, int out_size)
{
    const float* x      = (const float*)d_in[0];
    const float* attn   = (const float*)d_in[1];
    const int*   flows  = (const int*)  d_in[2];
    const float* v_w    = (const float*)d_in[3];
    const float* proj_w = (const float*)d_in[4];
    const float* proj_b = (const float*)d_in[5];
    float* out = (float*)d_out;

    float *xt, *wv, *wp, *v_buf, *agg_buf;
    cudaGetSymbolAddress((void**)&xt,      g_xt);
    cudaGetSymbolAddress((void**)&wv,      g_wv);
    cudaGetSymbolAddress((void**)&wp,      g_wp);
    cudaGetSymbolAddress((void**)&v_buf,   g_v);
    cudaGetSymbolAddress((void**)&agg_buf, g_agg);

    cudaFuncSetAttribute(gemm_tf32_mma_kernel,
                         cudaFuncAttributeMaxDynamicSharedMemorySize, DSMEM_BYTES);

    // 0) pre-round x and weights to tf32
    {
        const int n4x = MDIM * CC / 4;     // 4194304
        cvt_tf32_kernel<<<n4x / 256, 256>>>(x, xt, n4x);
        const int n4w = CC * CC / 4;       // 16384
        cvt_tf32_kernel<<<n4w / 256, 256>>>(v_w, wv, n4w);
        cvt_tf32_kernel<<<n4w / 256, 256>>>(proj_w, wp, n4w);
    }

    dim3 ggrid(CC / GEMM_BN, MDIM / GEMM_BM);   // (2, 512)

    // 1) v = x @ v_w.T
    gemm_tf32_mma_kernel<<<ggrid, 256, DSMEM_BYTES>>>(xt, wv, nullptr, v_buf);

    // 2) gather + weighted aggregation (emits tf32-rounded agg)
    {
        const int total_warps = HDN * TT * HH * WW / 4;   // 131072
        gather_agg_kernel<<<total_warps / 8, 256>>>(v_buf, attn, flows, agg_buf);
    }

    // 3) out = agg @ proj_w.T + proj_b
    gemm_tf32_mma_kernel<<<ggrid, 256, DSMEM_BYTES>>>(agg_buf, wp, proj_b, out);
}

// round 7
// speedup vs baseline: 3.2009x; 1.0314x over previous
#include <cuda_runtime.h>
#include <cstdint>

// -------------------- problem constants --------------------
#define TT   4
#define HH   128
#define WW   128
#define CC   256
#define HDN  8
#define KNBR 9
#define FF   32
#define MDIM (TT*HH*WW)   // 65536

// scratch (device globals; no runtime allocation allowed)
__device__ float g_v[(size_t)MDIM * CC];     // v = x @ v_w.T (fp32)
__device__ float g_agg[(size_t)MDIM * CC];   // aggregated (tf32-rounded bits)

// -------------------- helpers --------------------
__device__ __forceinline__ uint32_t smem_u32(const void* p) {
    uint32_t a;
    asm("{ .reg .u64 t; cvta.to.shared.u64 t, %1; cvt.u32.u64 %0, t; }" : "=r"(a) : "l"(p));
    return a;
}
// f32 -> tf32 (RNA); b32 in, b32 out
__device__ __forceinline__ uint32_t f2tf32(float x) {
    uint32_t r; asm("cvt.rna.tf32.f32 %0, %1;" : "=r"(r) : "f"(x)); return r;
}
__device__ __forceinline__ uint32_t rnd_u(uint32_t u) {
    uint32_t r; asm("cvt.rna.tf32.f32 %0, %1;" : "=r"(r) : "f"(__uint_as_float(u))); return r;
}
// Swizzle<3,4,3>
__device__ __forceinline__ uint32_t swz(uint32_t off) {
    return off ^ ((off >> 3) & 0x70);
}
__device__ __forceinline__ void cp_async16(uint32_t dst, const void* src) {
    asm volatile("cp.async.cg.shared.global [%0], [%1], 16;" :: "r"(dst), "l"(src));
}
__device__ __forceinline__ void cp_commit() {
    asm volatile("cp.async.commit_group;" ::: "memory");
}
template <int N>
__device__ __forceinline__ void cp_wait() {
    asm volatile("cp.async.wait_group %0;" :: "n"(N) : "memory");
}
__device__ __forceinline__ void ldmatrix_x4(uint32_t& r0, uint32_t& r1, uint32_t& r2, uint32_t& r3,
                                            uint32_t addr) {
    asm volatile("ldmatrix.sync.aligned.m8n8.x4.shared.b16 {%0,%1,%2,%3}, [%4];"
                 : "=r"(r0), "=r"(r1), "=r"(r2), "=r"(r3) : "r"(addr));
}
__device__ __forceinline__ void mma_tf32(float& c0, float& c1, float& c2, float& c3,
                                         uint32_t a0, uint32_t a1, uint32_t a2, uint32_t a3,
                                         uint32_t b0, uint32_t b1) {
    asm volatile("mma.sync.aligned.m16n8k8.row.col.f32.tf32.tf32.f32 "
                 "{%0,%1,%2,%3}, {%4,%5,%6,%7}, {%8,%9}, {%0,%1,%2,%3};"
                 : "+f"(c0), "+f"(c1), "+f"(c2), "+f"(c3)
                 : "r"(a0), "r"(a1), "r"(a2), "r"(a3), "r"(b0), "r"(b1));
}

// -------------------- tf32 mma.sync GEMM (cp.async, 3-stage) --------------------
// C[m,n] = sum_k A[m,k]*B[n,k] (+bias[n]); M=65536, N=256, K=256.
// CVT_A / CVT_B: round the respective ldmatrix fragments f32->tf32 (RNA) in-register.
// CTA tile 128x128, BK=32, 3-stage cp.async pipeline, 8 warps 2(m)x4(n).
#define GEMM_BM 128
#define GEMM_BN 128
#define GEMM_BK 32
#define TILE_BYTES (128 * 32 * 4)          // 16 KB
#define BUF_BYTES  (2 * TILE_BYTES)        // A+B per stage = 32 KB
#define NSTAGE 3
#define DSMEM_BYTES (NSTAGE * BUF_BYTES)   // 96 KB
#define NKT (CC / GEMM_BK)                 // 8

template <bool CVT_A, bool CVT_B>
__global__ __launch_bounds__(256, 2)
void gemm_tf32_mma_kernel(const float* __restrict__ A,
                          const float* __restrict__ Bw,
                          const float* __restrict__ bias,
                          float* __restrict__ C)
{
    extern __shared__ char sm[];
    const int tid = threadIdx.x;
    const int wid = tid >> 5;
    const int lane = tid & 31;
    const int warp_m = wid >> 2;      // 0..1
    const int warp_n = wid & 3;       // 0..3
    const int bm = blockIdx.y * GEMM_BM;
    const int bn = blockIdx.x * GEMM_BN;

    const uint32_t smbase = smem_u32(sm);

    // staging: thread handles float4 col st_c4 of rows st_row0 + 32*i
    const int st_c4  = tid & 7;
    const int st_row0 = tid >> 3;
    uint32_t st_off[4];
    #pragma unroll
    for (int i = 0; i < 4; i++)
        st_off[i] = swz((uint32_t)(st_row0 + 32 * i) * 128 + st_c4 * 16);

    const float* Abase = A + (size_t)(bm + st_row0) * CC + st_c4 * 4;
    const float* Bbase = Bw + (size_t)(bn + st_row0) * CC + st_c4 * 4;

    // prologue: issue stages 0 and 1
    #pragma unroll
    for (int s = 0; s < 2; s++) {
        const uint32_t abuf = smbase + s * BUF_BYTES;
        #pragma unroll
        for (int i = 0; i < 4; i++) {
            cp_async16(abuf + st_off[i],              Abase + (size_t)i * 32 * CC + s * GEMM_BK);
            cp_async16(abuf + TILE_BYTES + st_off[i], Bbase + (size_t)i * 32 * CC + s * GEMM_BK);
        }
        cp_commit();
    }

    float acc[4][4][4];
    #pragma unroll
    for (int mt = 0; mt < 4; mt++)
        #pragma unroll
        for (int nt = 0; nt < 4; nt++)
            #pragma unroll
            for (int r = 0; r < 4; r++)
                acc[mt][nt][r] = 0.0f;

    // ldmatrix per-lane address components
    const int a_row_in = (lane & 7) + ((lane >> 3) & 1) * 8;
    const int a_chunk_hi = (lane >> 4);
    const int b_nt_off = (lane >> 4) * 8;
    const int b_row_in = (lane & 7);
    const int b_chunk_hi = (lane >> 3) & 1;

    #pragma unroll
    for (int kt = 0; kt < NKT; kt++) {
        if (kt + 1 < NKT) cp_wait<1>(); else cp_wait<0>();
        __syncthreads();
        // single sync per kt: all warps finished compute of kt-1 before this
        // point, so the (kt+2)%3 buffer (== (kt-1)%3) is free to refill.
        if (kt + 2 < NKT) {
            const uint32_t abuf = smbase + ((kt + 2) % NSTAGE) * BUF_BYTES;
            #pragma unroll
            for (int i = 0; i < 4; i++) {
                cp_async16(abuf + st_off[i],              Abase + (size_t)i * 32 * CC + (kt + 2) * GEMM_BK);
                cp_async16(abuf + TILE_BYTES + st_off[i], Bbase + (size_t)i * 32 * CC + (kt + 2) * GEMM_BK);
            }
            cp_commit();
        }

        const uint32_t abuf = smbase + (kt % NSTAGE) * BUF_BYTES;
        const uint32_t bbuf = abuf + TILE_BYTES;

        #pragma unroll
        for (int kk = 0; kk < 4; kk++) {
            uint32_t af[4][4];
            #pragma unroll
            for (int mt = 0; mt < 4; mt++) {
                const int row = warp_m * 64 + mt * 16 + a_row_in;
                const uint32_t off = swz((uint32_t)row * 128 + (kk * 2 + a_chunk_hi) * 16);
                ldmatrix_x4(af[mt][0], af[mt][1], af[mt][2], af[mt][3], abuf + off);
                if (CVT_A) {
                    af[mt][0] = rnd_u(af[mt][0]); af[mt][1] = rnd_u(af[mt][1]);
                    af[mt][2] = rnd_u(af[mt][2]); af[mt][3] = rnd_u(af[mt][3]);
                }
            }
            uint32_t bf[4][2];
            #pragma unroll
            for (int pair = 0; pair < 2; pair++) {
                const int row = warp_n * 32 + pair * 16 + b_nt_off + b_row_in;
                const uint32_t off = swz((uint32_t)row * 128 + (kk * 2 + b_chunk_hi) * 16);
                uint32_t r0, r1, r2, r3;
                ldmatrix_x4(r0, r1, r2, r3, bbuf + off);
                if (CVT_B) {
                    r0 = rnd_u(r0); r1 = rnd_u(r1); r2 = rnd_u(r2); r3 = rnd_u(r3);
                }
                bf[pair * 2 + 0][0] = r0; bf[pair * 2 + 0][1] = r1;
                bf[pair * 2 + 1][0] = r2; bf[pair * 2 + 1][1] = r3;
            }
            #pragma unroll
            for (int mt = 0; mt < 4; mt++)
                #pragma unroll
                for (int nt = 0; nt < 4; nt++)
                    mma_tf32(acc[mt][nt][0], acc[mt][nt][1], acc[mt][nt][2], acc[mt][nt][3],
                             af[mt][0], af[mt][1], af[mt][2], af[mt][3],
                             bf[nt][0], bf[nt][1]);
        }
    }

    // epilogue
    const int er = warp_m * 64 + (lane >> 2);
    const int ec = warp_n * 32 + (lane & 3) * 2;
    #pragma unroll
    for (int mt = 0; mt < 4; mt++) {
        #pragma unroll
        for (int nt = 0; nt < 4; nt++) {
            const int row = bm + er + mt * 16;
            const int col = bn + ec + nt * 8;
            float2 lo = make_float2(acc[mt][nt][0], acc[mt][nt][1]);
            float2 hi = make_float2(acc[mt][nt][2], acc[mt][nt][3]);
            if (bias) {
                const float b0 = bias[col], b1 = bias[col + 1];
                lo.x += b0; lo.y += b1; hi.x += b0; hi.y += b1;
            }
            *(float2*)(C + (size_t)row * CC + col)       = lo;
            *(float2*)(C + (size_t)(row + 8) * CC + col) = hi;
        }
    }
}

// -------------------- flow-guided gather + aggregation --------------------
// CTA = (hd, t, 16x16 h/w tile) for L1 reuse of neighbor rows.
// 256 threads, 8 items each: item -> (pos_local, fq). Output tf32-rounded.
__global__ __launch_bounds__(256)
void gather_agg_kernel(const float* __restrict__ v,
                       const float* __restrict__ attn,
                       const int*   __restrict__ flows,
                       float* __restrict__ agg)
{
    int b = blockIdx.x;
    const int w0 = (b & 7) << 4; b >>= 3;
    const int h0 = (b & 7) << 4; b >>= 3;
    const int t  = b & 3;
    const int hd = b >> 2;

    const int tid = threadIdx.x;
    #pragma unroll
    for (int i = 0; i < 8; i++) {
        const int item = tid + (i << 8);      // 0..2047
        const int fq = item & 7;              // float4 index in 32 features
        const int pl = item >> 3;             // 0..255
        const int w = w0 + (pl & 15);
        const int h = h0 + (pl >> 4);

        const int pos = ((hd * TT + t) * HH + h) * WW + w;
        const size_t abase = (size_t)pos * KNBR;
        const size_t fbase = (size_t)pos * (KNBR * 3);

        float4 acc = make_float4(0.f, 0.f, 0.f, 0.f);
        #pragma unroll
        for (int k = 0; k < KNBR; k++) {
            const float wk = __ldg(attn + abase + k);
            const int dt = __ldg(flows + fbase + k * 3 + 0);
            const int dh = __ldg(flows + fbase + k * 3 + 1);
            const int dw = __ldg(flows + fbase + k * 3 + 2);
            const int tt = min(max(t + dt, 0), TT - 1);
            const int hh = min(max(h + dh, 0), HH - 1);
            const int ww = min(max(w + dw, 0), WW - 1);
            const float4 vv = *(const float4*)(v +
                ((size_t)((tt * HH + hh) * WW + ww)) * CC + hd * FF + fq * 4);
            acc.x += wk * vv.x; acc.y += wk * vv.y;
            acc.z += wk * vv.z; acc.w += wk * vv.w;
        }
        uint4 o;
        o.x = f2tf32(acc.x); o.y = f2tf32(acc.y);
        o.z = f2tf32(acc.z); o.w = f2tf32(acc.w);
        *(uint4*)(agg + ((size_t)((t * HH + h) * WW + w)) * CC + hd * FF + fq * 4) = o;
    }
}

// -------------------- launch --------------------
extern "C" void kernel_launch(void* const* d_in, const int* in_sizes, int n_in,
                              void* d_out, int out_size)
{
    const float* x      = (const float*)d_in[0];
    const float* attn   = (const float*)d_in[1];
    const int*   flows  = (const int*)  d_in[2];
    const float* v_w    = (const float*)d_in[3];
    const float* proj_w = (const float*)d_in[4];
    const float* proj_b = (const float*)d_in[5];
    float* out = (float*)d_out;

    float *v_buf, *agg_buf;
    cudaGetSymbolAddress((void**)&v_buf,   g_v);
    cudaGetSymbolAddress((void**)&agg_buf, g_agg);

    cudaFuncSetAttribute(gemm_tf32_mma_kernel<true, true>,
                         cudaFuncAttributeMaxDynamicSharedMemorySize, DSMEM_BYTES);
    cudaFuncSetAttribute(gemm_tf32_mma_kernel<false, true>,
                         cudaFuncAttributeMaxDynamicSharedMemorySize, DSMEM_BYTES);

    dim3 ggrid(CC / GEMM_BN, MDIM / GEMM_BM);   // (2, 512)

    // 1) v = x @ v_w.T   (round A and B fragments in-register)
    gemm_tf32_mma_kernel<true, true><<<ggrid, 256, DSMEM_BYTES>>>(x, v_w, nullptr, v_buf);

    // 2) gather + weighted aggregation (16x16 tiles; emits tf32-rounded agg)
    {
        const int blocks = HDN * TT * 8 * 8;     // 2048
        gather_agg_kernel<<<blocks, 256>>>(v_buf, attn, flows, agg_buf);
    }

    // 3) out = agg @ proj_w.T + proj_b  (A pre-rounded by gather; round B in-register)
    gemm_tf32_mma_kernel<false, true><<<ggrid, 256, DSMEM_BYTES>>>(agg_buf, proj_w, proj_b, out);
}

// round 8
// speedup vs baseline: 3.3431x; 1.0444x over previous
#include <cuda_runtime.h>
#include <cstdint>

// -------------------- problem constants --------------------
#define TT   4
#define HH   128
#define WW   128
#define CC   256
#define HDN  8
#define KNBR 9
#define FF   32
#define MDIM (TT*HH*WW)   // 65536

// scratch (device globals; no runtime allocation allowed)
__device__ float g_v[(size_t)MDIM * CC];     // v = x @ v_w.T (fp32)
__device__ float g_agg[(size_t)MDIM * CC];   // aggregated (tf32-rounded bits)
__device__ float g_wv[(size_t)CC * CC];      // v_w tf32-rounded
__device__ float g_wp[(size_t)CC * CC];      // proj_w tf32-rounded

// -------------------- helpers --------------------
__device__ __forceinline__ uint32_t smem_u32(const void* p) {
    uint32_t a;
    asm("{ .reg .u64 t; cvta.to.shared.u64 t, %1; cvt.u32.u64 %0, t; }" : "=r"(a) : "l"(p));
    return a;
}
// f32 -> tf32 (RNA); b32 out
__device__ __forceinline__ uint32_t f2tf32(float x) {
    uint32_t r; asm("cvt.rna.tf32.f32 %0, %1;" : "=r"(r) : "f"(x)); return r;
}
__device__ __forceinline__ uint32_t rnd_u(uint32_t u) {
    uint32_t r; asm("cvt.rna.tf32.f32 %0, %1;" : "=r"(r) : "f"(__uint_as_float(u))); return r;
}
// Swizzle<3,4,3>
__device__ __forceinline__ uint32_t swz(uint32_t off) {
    return off ^ ((off >> 3) & 0x70);
}
__device__ __forceinline__ void cp_async16(uint32_t dst, const void* src) {
    asm volatile("cp.async.cg.shared.global [%0], [%1], 16;" :: "r"(dst), "l"(src));
}
__device__ __forceinline__ void cp_commit() {
    asm volatile("cp.async.commit_group;" ::: "memory");
}
template <int N>
__device__ __forceinline__ void cp_wait() {
    asm volatile("cp.async.wait_group %0;" :: "n"(N) : "memory");
}
__device__ __forceinline__ void ldmatrix_x4(uint32_t& r0, uint32_t& r1, uint32_t& r2, uint32_t& r3,
                                            uint32_t addr) {
    asm volatile("ldmatrix.sync.aligned.m8n8.x4.shared.b16 {%0,%1,%2,%3}, [%4];"
                 : "=r"(r0), "=r"(r1), "=r"(r2), "=r"(r3) : "r"(addr));
}
__device__ __forceinline__ void mma_tf32(float& c0, float& c1, float& c2, float& c3,
                                         uint32_t a0, uint32_t a1, uint32_t a2, uint32_t a3,
                                         uint32_t b0, uint32_t b1) {
    asm volatile("mma.sync.aligned.m16n8k8.row.col.f32.tf32.tf32.f32 "
                 "{%0,%1,%2,%3}, {%4,%5,%6,%7}, {%8,%9}, {%0,%1,%2,%3};"
                 : "+f"(c0), "+f"(c1), "+f"(c2), "+f"(c3)
                 : "r"(a0), "r"(a1), "r"(a2), "r"(a3), "r"(b0), "r"(b1));
}

// -------------------- tf32 pre-conversion (weights only; tiny) --------------------
__global__ __launch_bounds__(256)
void cvt_tf32_kernel(const float* __restrict__ in, float* __restrict__ out, int n4) {
    int i = blockIdx.x * blockDim.x + threadIdx.x;
    if (i < n4) {
        float4 v = ((const float4*)in)[i];
        uint4 o;
        o.x = f2tf32(v.x); o.y = f2tf32(v.y);
        o.z = f2tf32(v.z); o.w = f2tf32(v.w);
        ((uint4*)out)[i] = o;
    }
}

// -------------------- tf32 mma.sync GEMM (cp.async, 3-stage) --------------------
#define GEMM_BM 128
#define GEMM_BN 128
#define GEMM_BK 32
#define TILE_BYTES (128 * 32 * 4)          // 16 KB
#define BUF_BYTES  (2 * TILE_BYTES)        // A+B per stage = 32 KB
#define NSTAGE 3
#define DSMEM_BYTES (NSTAGE * BUF_BYTES)   // 96 KB
#define NKT (CC / GEMM_BK)                 // 8

template <bool CVT_A, bool CVT_B>
__global__ __launch_bounds__(256, 2)
void gemm_tf32_mma_kernel(const float* __restrict__ A,
                          const float* __restrict__ Bw,
                          const float* __restrict__ bias,
                          float* __restrict__ C)
{
    extern __shared__ char sm[];
    const int tid = threadIdx.x;
    const int wid = tid >> 5;
    const int lane = tid & 31;
    const int warp_m = wid >> 2;
    const int warp_n = wid & 3;
    const int bm = blockIdx.y * GEMM_BM;
    const int bn = blockIdx.x * GEMM_BN;

    const uint32_t smbase = smem_u32(sm);

    const int st_c4  = tid & 7;
    const int st_row0 = tid >> 3;
    uint32_t st_off[4];
    #pragma unroll
    for (int i = 0; i < 4; i++)
        st_off[i] = swz((uint32_t)(st_row0 + 32 * i) * 128 + st_c4 * 16);

    const float* Abase = A + (size_t)(bm + st_row0) * CC + st_c4 * 4;
    const float* Bbase = Bw + (size_t)(bn + st_row0) * CC + st_c4 * 4;

    #pragma unroll
    for (int s = 0; s < 2; s++) {
        const uint32_t abuf = smbase + s * BUF_BYTES;
        #pragma unroll
        for (int i = 0; i < 4; i++) {
            cp_async16(abuf + st_off[i],              Abase + (size_t)i * 32 * CC + s * GEMM_BK);
            cp_async16(abuf + TILE_BYTES + st_off[i], Bbase + (size_t)i * 32 * CC + s * GEMM_BK);
        }
        cp_commit();
    }

    float acc[4][4][4];
    #pragma unroll
    for (int mt = 0; mt < 4; mt++)
        #pragma unroll
        for (int nt = 0; nt < 4; nt++)
            #pragma unroll
            for (int r = 0; r < 4; r++)
                acc[mt][nt][r] = 0.0f;

    const int a_row_in = (lane & 7) + ((lane >> 3) & 1) * 8;
    const int a_chunk_hi = (lane >> 4);
    const int b_nt_off = (lane >> 4) * 8;
    const int b_row_in = (lane & 7);
    const int b_chunk_hi = (lane >> 3) & 1;

    #pragma unroll
    for (int kt = 0; kt < NKT; kt++) {
        if (kt + 1 < NKT) cp_wait<1>(); else cp_wait<0>();
        __syncthreads();
        if (kt + 2 < NKT) {
            const uint32_t abuf = smbase + ((kt + 2) % NSTAGE) * BUF_BYTES;
            #pragma unroll
            for (int i = 0; i < 4; i++) {
                cp_async16(abuf + st_off[i],              Abase + (size_t)i * 32 * CC + (kt + 2) * GEMM_BK);
                cp_async16(abuf + TILE_BYTES + st_off[i], Bbase + (size_t)i * 32 * CC + (kt + 2) * GEMM_BK);
            }
            cp_commit();
        }

        const uint32_t abuf = smbase + (kt % NSTAGE) * BUF_BYTES;
        const uint32_t bbuf = abuf + TILE_BYTES;

        #pragma unroll
        for (int kk = 0; kk < 4; kk++) {
            uint32_t af[4][4];
            #pragma unroll
            for (int mt = 0; mt < 4; mt++) {
                const int row = warp_m * 64 + mt * 16 + a_row_in;
                const uint32_t off = swz((uint32_t)row * 128 + (kk * 2 + a_chunk_hi) * 16);
                ldmatrix_x4(af[mt][0], af[mt][1], af[mt][2], af[mt][3], abuf + off);
                if (CVT_A) {
                    af[mt][0] = rnd_u(af[mt][0]); af[mt][1] = rnd_u(af[mt][1]);
                    af[mt][2] = rnd_u(af[mt][2]); af[mt][3] = rnd_u(af[mt][3]);
                }
            }
            uint32_t bf[4][2];
            #pragma unroll
            for (int pair = 0; pair < 2; pair++) {
                const int row = warp_n * 32 + pair * 16 + b_nt_off + b_row_in;
                const uint32_t off = swz((uint32_t)row * 128 + (kk * 2 + b_chunk_hi) * 16);
                uint32_t r0, r1, r2, r3;
                ldmatrix_x4(r0, r1, r2, r3, bbuf + off);
                if (CVT_B) {
                    r0 = rnd_u(r0); r1 = rnd_u(r1); r2 = rnd_u(r2); r3 = rnd_u(r3);
                }
                bf[pair * 2 + 0][0] = r0; bf[pair * 2 + 0][1] = r1;
                bf[pair * 2 + 1][0] = r2; bf[pair * 2 + 1][1] = r3;
            }
            #pragma unroll
            for (int mt = 0; mt < 4; mt++)
                #pragma unroll
                for (int nt = 0; nt < 4; nt++)
                    mma_tf32(acc[mt][nt][0], acc[mt][nt][1], acc[mt][nt][2], acc[mt][nt][3],
                             af[mt][0], af[mt][1], af[mt][2], af[mt][3],
                             bf[nt][0], bf[nt][1]);
        }
    }

    const int er = warp_m * 64 + (lane >> 2);
    const int ec = warp_n * 32 + (lane & 3) * 2;
    #pragma unroll
    for (int mt = 0; mt < 4; mt++) {
        #pragma unroll
        for (int nt = 0; nt < 4; nt++) {
            const int row = bm + er + mt * 16;
            const int col = bn + ec + nt * 8;
            float2 lo = make_float2(acc[mt][nt][0], acc[mt][nt][1]);
            float2 hi = make_float2(acc[mt][nt][2], acc[mt][nt][3]);
            if (bias) {
                const float b0 = bias[col], b1 = bias[col + 1];
                lo.x += b0; lo.y += b1; hi.x += b0; hi.y += b1;
            }
            *(float2*)(C + (size_t)row * CC + col)       = lo;
            *(float2*)(C + (size_t)(row + 8) * CC + col) = hi;
        }
    }
}

// -------------------- flow-guided gather + aggregation (v2) --------------------
// Block = (hd, t, 16x16 h/w tile), 256 threads.
// Phase 1: thread = position; load 9 attn + 27 flows ONCE, compute clipped
//          v-row element offsets; stash (attn, vidx) in smem.
// Phase 2: fq-split (8 threads/position) reads smem (broadcast) and does only
//          the 9 coalesced 128B v-row loads per position. Output tf32-rounded.
__global__ __launch_bounds__(256)
void gather_agg_kernel(const float* __restrict__ v,
                       const float* __restrict__ attn,
                       const int*   __restrict__ flows,
                       float* __restrict__ agg)
{
    __shared__ float s_attn[256 * KNBR];
    __shared__ int   s_voff[256 * KNBR];

    int b = blockIdx.x;
    const int w0 = (b & 7) << 4; b >>= 3;
    const int h0 = (b & 7) << 4; b >>= 3;
    const int t  = b & 3;
    const int hd = b >> 2;

    const int tid = threadIdx.x;

    // ---- phase 1 ----
    {
        const int w = w0 + (tid & 15);
        const int h = h0 + (tid >> 4);
        const int pos = ((hd * TT + t) * HH + h) * WW + w;
        const size_t abase = (size_t)pos * KNBR;
        const size_t fbase = (size_t)pos * (KNBR * 3);
        #pragma unroll
        for (int k = 0; k < KNBR; k++) {
            s_attn[tid * KNBR + k] = __ldg(attn + abase + k);
            const int dt = __ldg(flows + fbase + k * 3 + 0);
            const int dh = __ldg(flows + fbase + k * 3 + 1);
            const int dw = __ldg(flows + fbase + k * 3 + 2);
            const int tt = min(max(t + dt, 0), TT - 1);
            const int hh = min(max(h + dh, 0), HH - 1);
            const int ww = min(max(w + dw, 0), WW - 1);
            s_voff[tid * KNBR + k] = ((tt * HH + hh) * WW + ww) * CC;
        }
    }
    __syncthreads();

    // ---- phase 2 ----
    const int fbyte = hd * FF;   // head feature base
    #pragma unroll
    for (int i = 0; i < 8; i++) {
        const int item = tid + (i << 8);      // 0..2047
        const int fq = item & 7;
        const int pl = item >> 3;             // 0..255
        const int w = w0 + (pl & 15);
        const int h = h0 + (pl >> 4);

        float4 acc = make_float4(0.f, 0.f, 0.f, 0.f);
        #pragma unroll
        for (int k = 0; k < KNBR; k++) {
            const float wk = s_attn[pl * KNBR + k];
            const int voff = s_voff[pl * KNBR + k];
            const float4 vv = *(const float4*)(v + voff + fbyte + fq * 4);
            acc.x += wk * vv.x; acc.y += wk * vv.y;
            acc.z += wk * vv.z; acc.w += wk * vv.w;
        }
        uint4 o;
        o.x = f2tf32(acc.x); o.y = f2tf32(acc.y);
        o.z = f2tf32(acc.z); o.w = f2tf32(acc.w);
        *(uint4*)(agg + ((size_t)((t * HH + h) * WW + w)) * CC + fbyte + fq * 4) = o;
    }
}

// -------------------- launch --------------------
extern "C" void kernel_launch(void* const* d_in, const int* in_sizes, int n_in,
                              void* d_out, int out_size)
{
    const float* x      = (const float*)d_in[0];
    const float* attn   = (const float*)d_in[1];
    const int*   flows  = (const int*)  d_in[2];
    const float* v_w    = (const float*)d_in[3];
    const float* proj_w = (const float*)d_in[4];
    const float* proj_b = (const float*)d_in[5];
    float* out = (float*)d_out;

    float *v_buf, *agg_buf, *wv, *wp;
    cudaGetSymbolAddress((void**)&v_buf,   g_v);
    cudaGetSymbolAddress((void**)&agg_buf, g_agg);
    cudaGetSymbolAddress((void**)&wv,      g_wv);
    cudaGetSymbolAddress((void**)&wp,      g_wp);

    cudaFuncSetAttribute(gemm_tf32_mma_kernel<true, false>,
                         cudaFuncAttributeMaxDynamicSharedMemorySize, DSMEM_BYTES);
    cudaFuncSetAttribute(gemm_tf32_mma_kernel<false, false>,
                         cudaFuncAttributeMaxDynamicSharedMemorySize, DSMEM_BYTES);

    // 0) pre-round weights (tiny: 2 x 256KB)
    {
        const int n4w = CC * CC / 4;   // 16384
        cvt_tf32_kernel<<<n4w / 256, 256>>>(v_w, wv, n4w);
        cvt_tf32_kernel<<<n4w / 256, 256>>>(proj_w, wp, n4w);
    }

    dim3 ggrid(CC / GEMM_BN, MDIM / GEMM_BM);   // (2, 512)

    // 1) v = x @ v_w.T   (A rounded in-register; B pre-rounded)
    gemm_tf32_mma_kernel<true, false><<<ggrid, 256, DSMEM_BYTES>>>(x, wv, nullptr, v_buf);

    // 2) gather + weighted aggregation (two-phase smem; emits tf32-rounded agg)
    {
        const int blocks = HDN * TT * 8 * 8;     // 2048
        gather_agg_kernel<<<blocks, 256>>>(v_buf, attn, flows, agg_buf);
    }

    // 3) out = agg @ proj_w.T + proj_b  (both operands pre-rounded)
    gemm_tf32_mma_kernel<false, false><<<ggrid, 256, DSMEM_BYTES>>>(agg_buf, wp, proj_b, out);
}

// round 9
// speedup vs baseline: 3.5004x; 1.0471x over previous
#include <cuda_runtime.h>
#include <cstdint>

// -------------------- problem constants --------------------
#define TT   4
#define HH   128
#define WW   128
#define CC   256
#define HDN  8
#define KNBR 9
#define FF   32
#define MDIM (TT*HH*WW)   // 65536

// scratch (device globals; no runtime allocation allowed)
__device__ float g_v[(size_t)MDIM * CC];     // v = x @ v_w.T (fp32)
__device__ float g_agg[(size_t)MDIM * CC];   // aggregated (tf32-rounded bits)
__device__ float g_wv[(size_t)CC * CC];      // v_w tf32-rounded
__device__ float g_wp[(size_t)CC * CC];      // proj_w tf32-rounded

// -------------------- helpers --------------------
__device__ __forceinline__ uint32_t smem_u32(const void* p) {
    uint32_t a;
    asm("{ .reg .u64 t; cvta.to.shared.u64 t, %1; cvt.u32.u64 %0, t; }" : "=r"(a) : "l"(p));
    return a;
}
// f32 -> tf32 (RNA); b32 out
__device__ __forceinline__ uint32_t f2tf32(float x) {
    uint32_t r; asm("cvt.rna.tf32.f32 %0, %1;" : "=r"(r) : "f"(x)); return r;
}
__device__ __forceinline__ uint32_t rnd_u(uint32_t u) {
    uint32_t r; asm("cvt.rna.tf32.f32 %0, %1;" : "=r"(r) : "f"(__uint_as_float(u))); return r;
}
// Swizzle<3,4,3>
__device__ __forceinline__ uint32_t swz(uint32_t off) {
    return off ^ ((off >> 3) & 0x70);
}
__device__ __forceinline__ void cp_async16(uint32_t dst, const void* src) {
    asm volatile("cp.async.cg.shared.global [%0], [%1], 16;" :: "r"(dst), "l"(src));
}
__device__ __forceinline__ void cp_commit() {
    asm volatile("cp.async.commit_group;" ::: "memory");
}
template <int N>
__device__ __forceinline__ void cp_wait() {
    asm volatile("cp.async.wait_group %0;" :: "n"(N) : "memory");
}
__device__ __forceinline__ void ldmatrix_x4(uint32_t& r0, uint32_t& r1, uint32_t& r2, uint32_t& r3,
                                            uint32_t addr) {
    asm volatile("ldmatrix.sync.aligned.m8n8.x4.shared.b16 {%0,%1,%2,%3}, [%4];"
                 : "=r"(r0), "=r"(r1), "=r"(r2), "=r"(r3) : "r"(addr));
}
__device__ __forceinline__ void mma_tf32(float& c0, float& c1, float& c2, float& c3,
                                         uint32_t a0, uint32_t a1, uint32_t a2, uint32_t a3,
                                         uint32_t b0, uint32_t b1) {
    asm volatile("mma.sync.aligned.m16n8k8.row.col.f32.tf32.tf32.f32 "
                 "{%0,%1,%2,%3}, {%4,%5,%6,%7}, {%8,%9}, {%0,%1,%2,%3};"
                 : "+f"(c0), "+f"(c1), "+f"(c2), "+f"(c3)
                 : "r"(a0), "r"(a1), "r"(a2), "r"(a3), "r"(b0), "r"(b1));
}

// -------------------- tf32 pre-conversion (weights only; tiny) --------------------
__global__ __launch_bounds__(256)
void cvt_tf32_kernel(const float* __restrict__ in, float* __restrict__ out, int n4) {
    int i = blockIdx.x * blockDim.x + threadIdx.x;
    if (i < n4) {
        float4 v = ((const float4*)in)[i];
        uint4 o;
        o.x = f2tf32(v.x); o.y = f2tf32(v.y);
        o.z = f2tf32(v.z); o.w = f2tf32(v.w);
        ((uint4*)out)[i] = o;
    }
}

// -------------------- tf32 mma.sync GEMM (cp.async, 3-stage) --------------------
#define GEMM_BM 128
#define GEMM_BN 128
#define GEMM_BK 32
#define TILE_BYTES (128 * 32 * 4)          // 16 KB
#define BUF_BYTES  (2 * TILE_BYTES)        // A+B per stage = 32 KB
#define NSTAGE 3
#define DSMEM_BYTES (NSTAGE * BUF_BYTES)   // 96 KB
#define NKT (CC / GEMM_BK)                 // 8

template <bool CVT_A, bool CVT_B>
__global__ __launch_bounds__(256, 2)
void gemm_tf32_mma_kernel(const float* __restrict__ A,
                          const float* __restrict__ Bw,
                          const float* __restrict__ bias,
                          float* __restrict__ C)
{
    extern __shared__ char sm[];
    const int tid = threadIdx.x;
    const int wid = tid >> 5;
    const int lane = tid & 31;
    const int warp_m = wid >> 2;
    const int warp_n = wid & 3;
    const int bm = blockIdx.y * GEMM_BM;
    const int bn = blockIdx.x * GEMM_BN;

    const uint32_t smbase = smem_u32(sm);

    const int st_c4  = tid & 7;
    const int st_row0 = tid >> 3;
    uint32_t st_off[4];
    #pragma unroll
    for (int i = 0; i < 4; i++)
        st_off[i] = swz((uint32_t)(st_row0 + 32 * i) * 128 + st_c4 * 16);

    const float* Abase = A + (size_t)(bm + st_row0) * CC + st_c4 * 4;
    const float* Bbase = Bw + (size_t)(bn + st_row0) * CC + st_c4 * 4;

    #pragma unroll
    for (int s = 0; s < 2; s++) {
        const uint32_t abuf = smbase + s * BUF_BYTES;
        #pragma unroll
        for (int i = 0; i < 4; i++) {
            cp_async16(abuf + st_off[i],              Abase + (size_t)i * 32 * CC + s * GEMM_BK);
            cp_async16(abuf + TILE_BYTES + st_off[i], Bbase + (size_t)i * 32 * CC + s * GEMM_BK);
        }
        cp_commit();
    }

    float acc[4][4][4];
    #pragma unroll
    for (int mt = 0; mt < 4; mt++)
        #pragma unroll
        for (int nt = 0; nt < 4; nt++)
            #pragma unroll
            for (int r = 0; r < 4; r++)
                acc[mt][nt][r] = 0.0f;

    const int a_row_in = (lane & 7) + ((lane >> 3) & 1) * 8;
    const int a_chunk_hi = (lane >> 4);
    const int b_nt_off = (lane >> 4) * 8;
    const int b_row_in = (lane & 7);
    const int b_chunk_hi = (lane >> 3) & 1;

    #pragma unroll
    for (int kt = 0; kt < NKT; kt++) {
        if (kt + 1 < NKT) cp_wait<1>(); else cp_wait<0>();
        __syncthreads();
        if (kt + 2 < NKT) {
            const uint32_t abuf = smbase + ((kt + 2) % NSTAGE) * BUF_BYTES;
            #pragma unroll
            for (int i = 0; i < 4; i++) {
                cp_async16(abuf + st_off[i],              Abase + (size_t)i * 32 * CC + (kt + 2) * GEMM_BK);
                cp_async16(abuf + TILE_BYTES + st_off[i], Bbase + (size_t)i * 32 * CC + (kt + 2) * GEMM_BK);
            }
            cp_commit();
        }

        const uint32_t abuf = smbase + (kt % NSTAGE) * BUF_BYTES;
        const uint32_t bbuf = abuf + TILE_BYTES;

        #pragma unroll
        for (int kk = 0; kk < 4; kk++) {
            uint32_t af[4][4];
            #pragma unroll
            for (int mt = 0; mt < 4; mt++) {
                const int row = warp_m * 64 + mt * 16 + a_row_in;
                const uint32_t off = swz((uint32_t)row * 128 + (kk * 2 + a_chunk_hi) * 16);
                ldmatrix_x4(af[mt][0], af[mt][1], af[mt][2], af[mt][3], abuf + off);
                if (CVT_A) {
                    af[mt][0] = rnd_u(af[mt][0]); af[mt][1] = rnd_u(af[mt][1]);
                    af[mt][2] = rnd_u(af[mt][2]); af[mt][3] = rnd_u(af[mt][3]);
                }
            }
            uint32_t bf[4][2];
            #pragma unroll
            for (int pair = 0; pair < 2; pair++) {
                const int row = warp_n * 32 + pair * 16 + b_nt_off + b_row_in;
                const uint32_t off = swz((uint32_t)row * 128 + (kk * 2 + b_chunk_hi) * 16);
                uint32_t r0, r1, r2, r3;
                ldmatrix_x4(r0, r1, r2, r3, bbuf + off);
                if (CVT_B) {
                    r0 = rnd_u(r0); r1 = rnd_u(r1); r2 = rnd_u(r2); r3 = rnd_u(r3);
                }
                bf[pair * 2 + 0][0] = r0; bf[pair * 2 + 0][1] = r1;
                bf[pair * 2 + 1][0] = r2; bf[pair * 2 + 1][1] = r3;
            }
            #pragma unroll
            for (int mt = 0; mt < 4; mt++)
                #pragma unroll
                for (int nt = 0; nt < 4; nt++)
                    mma_tf32(acc[mt][nt][0], acc[mt][nt][1], acc[mt][nt][2], acc[mt][nt][3],
                             af[mt][0], af[mt][1], af[mt][2], af[mt][3],
                             bf[nt][0], bf[nt][1]);
        }
    }

    const int er = warp_m * 64 + (lane >> 2);
    const int ec = warp_n * 32 + (lane & 3) * 2;
    #pragma unroll
    for (int mt = 0; mt < 4; mt++) {
        #pragma unroll
        for (int nt = 0; nt < 4; nt++) {
            const int row = bm + er + mt * 16;
            const int col = bn + ec + nt * 8;
            float2 lo = make_float2(acc[mt][nt][0], acc[mt][nt][1]);
            float2 hi = make_float2(acc[mt][nt][2], acc[mt][nt][3]);
            if (bias) {
                const float b0 = bias[col], b1 = bias[col + 1];
                lo.x += b0; lo.y += b1; hi.x += b0; hi.y += b1;
            }
            *(float2*)(C + (size_t)row * CC + col)       = lo;
            *(float2*)(C + (size_t)(row + 8) * CC + col) = hi;
        }
    }
}

// -------------------- flow-guided gather + aggregation (v3) --------------------
// Block = (hd, t, 16x16 h/w tile), 256 threads.
// Stage 0: COALESCED copy of the block's attn (16 segs x 144 floats) and flows
//          (16 segs x 432 ints) into smem — stride-1 per thread.
// Stage 1: thread = position; compute clipped v-row offsets from smem flows.
// Stage 2: fq-split (8 threads/position): 9 coalesced 128B v-row loads, weighted
//          sum, tf32-rounded store.
__global__ __launch_bounds__(256)
void gather_agg_kernel(const float* __restrict__ v,
                       const float* __restrict__ attn,
                       const int*   __restrict__ flows,
                       float* __restrict__ agg)
{
    __shared__ float s_attn[256 * KNBR];        // 9 KB, layout [pl*9 + k]
    __shared__ int   s_flows[256 * KNBR * 3];   // 27 KB, layout [pl*27 + k*3 + c]
    __shared__ int   s_voff[256 * KNBR];        // 9 KB

    int b = blockIdx.x;
    const int w0 = (b & 7) << 4; b >>= 3;
    const int h0 = (b & 7) << 4; b >>= 3;
    const int t  = b & 3;
    const int hd = b >> 2;

    const int tid = threadIdx.x;

    // ---- stage 0: coalesced staging ----
    // position of (h0+r, w0): base + r*WW; 16 consecutive w are contiguous.
    const size_t pos00 = ((size_t)((hd * TT + t) * HH + h0)) * WW + w0;
    {
        const float* ab = attn + pos00 * KNBR;
        #pragma unroll
        for (int j = tid; j < 16 * 144; j += 256) {      // 9 iters
            const int r = j / 144;
            const int c = j - r * 144;
            s_attn[r * 144 + c] = __ldg(ab + (size_t)r * (WW * KNBR) + c);
        }
        const int* fb = flows + pos00 * (KNBR * 3);
        #pragma unroll
        for (int j = tid; j < 16 * 432; j += 256) {      // 27 iters
            const int r = j / 432;
            const int c = j - r * 432;
            s_flows[r * 432 + c] = __ldg(fb + (size_t)r * (WW * KNBR * 3) + c);
        }
    }
    __syncthreads();

    // ---- stage 1: offsets ----
    {
        const int pl = tid;
        const int w = w0 + (pl & 15);
        const int h = h0 + (pl >> 4);
        #pragma unroll
        for (int k = 0; k < KNBR; k++) {
            const int dt = s_flows[pl * 27 + k * 3 + 0];
            const int dh = s_flows[pl * 27 + k * 3 + 1];
            const int dw = s_flows[pl * 27 + k * 3 + 2];
            const int tt = min(max(t + dt, 0), TT - 1);
            const int hh = min(max(h + dh, 0), HH - 1);
            const int ww = min(max(w + dw, 0), WW - 1);
            s_voff[pl * KNBR + k] = ((tt * HH + hh) * WW + ww) * CC;
        }
    }
    __syncthreads();

    // ---- stage 2: gather + weighted sum ----
    const int fbyte = hd * FF;
    #pragma unroll
    for (int i = 0; i < 8; i++) {
        const int item = tid + (i << 8);      // 0..2047
        const int fq = item & 7;
        const int pl = item >> 3;             // 0..255
        const int w = w0 + (pl & 15);
        const int h = h0 + (pl >> 4);

        float4 acc = make_float4(0.f, 0.f, 0.f, 0.f);
        #pragma unroll
        for (int k = 0; k < KNBR; k++) {
            const float wk = s_attn[pl * KNBR + k];
            const int voff = s_voff[pl * KNBR + k];
            const float4 vv = *(const float4*)(v + voff + fbyte + fq * 4);
            acc.x += wk * vv.x; acc.y += wk * vv.y;
            acc.z += wk * vv.z; acc.w += wk * vv.w;
        }
        uint4 o;
        o.x = f2tf32(acc.x); o.y = f2tf32(acc.y);
        o.z = f2tf32(acc.z); o.w = f2tf32(acc.w);
        *(uint4*)(agg + ((size_t)((t * HH + h) * WW + w)) * CC + fbyte + fq * 4) = o;
    }
}

// -------------------- launch --------------------
extern "C" void kernel_launch(void* const* d_in, const int* in_sizes, int n_in,
                              void* d_out, int out_size)
{
    const float* x      = (const float*)d_in[0];
    const float* attn   = (const float*)d_in[1];
    const int*   flows  = (const int*)  d_in[2];
    const float* v_w    = (const float*)d_in[3];
    const float* proj_w = (const float*)d_in[4];
    const float* proj_b = (const float*)d_in[5];
    float* out = (float*)d_out;

    float *v_buf, *agg_buf, *wv, *wp;
    cudaGetSymbolAddress((void**)&v_buf,   g_v);
    cudaGetSymbolAddress((void**)&agg_buf, g_agg);
    cudaGetSymbolAddress((void**)&wv,      g_wv);
    cudaGetSymbolAddress((void**)&wp,      g_wp);

    cudaFuncSetAttribute(gemm_tf32_mma_kernel<true, false>,
                         cudaFuncAttributeMaxDynamicSharedMemorySize, DSMEM_BYTES);
    cudaFuncSetAttribute(gemm_tf32_mma_kernel<false, false>,
                         cudaFuncAttributeMaxDynamicSharedMemorySize, DSMEM_BYTES);

    // 0) pre-round weights (tiny: 2 x 256KB)
    {
        const int n4w = CC * CC / 4;   // 16384
        cvt_tf32_kernel<<<n4w / 256, 256>>>(v_w, wv, n4w);
        cvt_tf32_kernel<<<n4w / 256, 256>>>(proj_w, wp, n4w);
    }

    dim3 ggrid(CC / GEMM_BN, MDIM / GEMM_BM);   // (2, 512)

    // 1) v = x @ v_w.T   (A rounded in-register; B pre-rounded)
    gemm_tf32_mma_kernel<true, false><<<ggrid, 256, DSMEM_BYTES>>>(x, wv, nullptr, v_buf);

    // 2) gather + weighted aggregation (coalesced staging; emits tf32-rounded agg)
    {
        const int blocks = HDN * TT * 8 * 8;     // 2048
        gather_agg_kernel<<<blocks, 256>>>(v_buf, attn, flows, agg_buf);
    }

    // 3) out = agg @ proj_w.T + proj_b  (both operands pre-rounded)
    gemm_tf32_mma_kernel<false, false><<<ggrid, 256, DSMEM_BYTES>>>(agg_buf, wp, proj_b, out);
}